// round 2
// baseline (speedup 1.0000x reference)
#include <cuda_runtime.h>

#define NNODES 50000
#define DFEAT 128

// ---- scratch (device globals: no allocation allowed) ----
__device__ __align__(256) float  g_H[NNODES * DFEAT];   // h = (1+eps)*x + agg
__device__ __align__(256) float  g_Z1[NNODES * DFEAT];  // pre-BN output of linear1
__device__ __align__(256) float  g_Wt1[DFEAT * DFEAT];  // W1 transposed [k][o]
__device__ __align__(256) float  g_Wt2[DFEAT * DFEAT];  // W2 transposed [k][o]
__device__ __align__(256) double g_stats[512];          // sum1,sq1,sum2,sq2 (128 each)
__device__ __align__(256) float  g_bn[512];             // scale1,shift1 ; scale2,shift2
__device__ int g_is64;                                  // edge_index dtype flag

// ---- probe edge_index dtype (int64 vs int32), deterministic ----
__global__ void detect_kernel(const void* eiv, int E, int N) {
    __shared__ int bad;
    if (threadIdx.x == 0) bad = 0;
    __syncthreads();
    const long long* p = (const long long*)eiv;
    int n = E < 1024 ? E : 1024;   // stays within buffer under either dtype
    for (int i = threadIdx.x; i < n; i += blockDim.x) {
        long long v = p[i];
        if (v < 0 || v >= (long long)N) atomicOr(&bad, 1);
    }
    __syncthreads();
    if (threadIdx.x == 0) g_is64 = bad ? 0 : 1;
}

// ---- prep: transpose weights + zero stats accumulators (every launch) ----
__global__ void prep_kernel(const float* __restrict__ W1, const float* __restrict__ W2) {
    int idx = blockIdx.x * blockDim.x + threadIdx.x;
    if (idx < 16384) {
        g_Wt1[(idx & 127) * 128 + (idx >> 7)] = W1[idx];
    } else if (idx < 32768) {
        int j = idx - 16384;
        g_Wt2[(j & 127) * 128 + (j >> 7)] = W2[j];
    } else if (idx < 33280) {
        g_stats[idx - 32768] = 0.0;
    }
}

// ---- h = (1+eps) * x ----
__global__ void init_h_kernel(const float* __restrict__ x, const float* __restrict__ eps, int n4) {
    int idx = blockIdx.x * blockDim.x + threadIdx.x;
    if (idx >= n4) return;
    float c = 1.0f + *eps;
    float4 v = ((const float4*)x)[idx];
    v.x *= c; v.y *= c; v.z *= c; v.w *= c;
    ((float4*)g_H)[idx] = v;
}

// ---- edge scatter-add: one warp per edge, vector L2 reductions ----
__global__ void scatter_kernel(const float* __restrict__ x,
                               const void* __restrict__ eiv, int E) {
    int e = (blockIdx.x * blockDim.x + threadIdx.x) >> 5;
    if (e >= E) return;
    int lane = threadIdx.x & 31;
    long long s, d;
    if (g_is64) {
        const long long* ei = (const long long*)eiv;
        s = __ldg(&ei[e]);
        d = __ldg(&ei[E + e]);
    } else {
        const int* ei = (const int*)eiv;
        s = __ldg(&ei[e]);
        d = __ldg(&ei[E + e]);
    }
    float4 v = ((const float4*)(x + s * 128))[lane];
    float* dp = g_H + d * 128 + (lane << 2);
    asm volatile("red.global.add.v4.f32 [%0], {%1,%2,%3,%4};"
                 :: "l"(dp), "f"(v.x), "f"(v.y), "f"(v.z), "f"(v.w) : "memory");
}

// ---- GEMM: Z[m][o] = bias[o] + sum_k f(A[m][k]) * W[o][k]
// MODE 0: A=g_H,  f=identity,               Z=g_Z1
// MODE 1: A=g_Z1, f=relu(bn1(.)) (fused),   Z=Zout (harness d_out)
// Block: 64 rows x 128 cols (full K=128 in smem). 128 threads, 8x8 reg tile.
#define GEMM_SMEM_BYTES ((64 * 129 + 128 * 128 + 256) * 4)

template <int MODE>
__global__ void __launch_bounds__(128) gemm_bn(const float* __restrict__ bias,
                                               float* __restrict__ Zout, int M) {
    extern __shared__ float smem[];
    float (*As)[129] = (float(*)[129])smem;       // 64 x 129 (padded)
    float* Ws      = smem + 64 * 129;             // [k][o], 128x128
    float* s_scale = Ws + 16384;
    float* s_shift = s_scale + 128;

    const float* A  = MODE ? g_Z1 : g_H;
    const float* Wt = MODE ? g_Wt2 : g_Wt1;
    float* Z        = MODE ? Zout : g_Z1;

    int tid = threadIdx.x;
    int m0 = blockIdx.x * 64;

    if (MODE) {
        s_scale[tid] = g_bn[tid];
        s_shift[tid] = g_bn[128 + tid];
        __syncthreads();
    }

    // load W tile (coalesced, already transposed in gmem)
    const float4* Wt4 = (const float4*)Wt;
    float4* Ws4 = (float4*)Ws;
#pragma unroll
    for (int i = 0; i < 32; i++)
        Ws4[i * 128 + tid] = Wt4[i * 128 + tid];

    // load A tile (apply BN1+ReLU on the fly in MODE 1)
#pragma unroll
    for (int i = 0; i < 16; i++) {
        int idx = i * 128 + tid;
        int m = idx >> 5, k4 = idx & 31;
        int gm = m0 + m;
        float4 v = make_float4(0.f, 0.f, 0.f, 0.f);
        if (gm < M) v = ((const float4*)A)[(size_t)gm * 32 + k4];
        int k = k4 * 4;
        if (MODE) {
            v.x = fmaxf(fmaf(v.x, s_scale[k + 0], s_shift[k + 0]), 0.f);
            v.y = fmaxf(fmaf(v.y, s_scale[k + 1], s_shift[k + 1]), 0.f);
            v.z = fmaxf(fmaf(v.z, s_scale[k + 2], s_shift[k + 2]), 0.f);
            v.w = fmaxf(fmaf(v.w, s_scale[k + 3], s_shift[k + 3]), 0.f);
        }
        As[m][k + 0] = v.x; As[m][k + 1] = v.y;
        As[m][k + 2] = v.z; As[m][k + 3] = v.w;
    }
    __syncthreads();

    int ty = tid >> 4, tx = tid & 15;
    float acc[8][8];
#pragma unroll
    for (int i = 0; i < 8; i++)
#pragma unroll
        for (int j = 0; j < 8; j++) acc[i][j] = 0.f;

#pragma unroll 4
    for (int k = 0; k < 128; k++) {
        float a[8];
#pragma unroll
        for (int i = 0; i < 8; i++) a[i] = As[ty * 8 + i][k];
        float4 wa = *(const float4*)(Ws + k * 128 + tx * 8);
        float4 wb = *(const float4*)(Ws + k * 128 + tx * 8 + 4);
        float w[8] = {wa.x, wa.y, wa.z, wa.w, wb.x, wb.y, wb.z, wb.w};
#pragma unroll
        for (int i = 0; i < 8; i++)
#pragma unroll
            for (int j = 0; j < 8; j++)
                acc[i][j] = fmaf(a[i], w[j], acc[i][j]);
    }

    float bi[8];
#pragma unroll
    for (int j = 0; j < 8; j++) bi[j] = bias[tx * 8 + j];
#pragma unroll
    for (int i = 0; i < 8; i++) {
        int gm = m0 + ty * 8 + i;
        if (gm < M) {
            float4 o0 = make_float4(acc[i][0] + bi[0], acc[i][1] + bi[1],
                                    acc[i][2] + bi[2], acc[i][3] + bi[3]);
            float4 o1 = make_float4(acc[i][4] + bi[4], acc[i][5] + bi[5],
                                    acc[i][6] + bi[6], acc[i][7] + bi[7]);
            float4* zp = (float4*)(Z + (size_t)gm * 128);
            zp[tx * 2] = o0;
            zp[tx * 2 + 1] = o1;
        }
    }
}

// ---- per-column sum / sum-of-squares over all rows (double accumulation) ----
template <int MODE>
__global__ void colstats_kernel(const float* __restrict__ Zext, int M) {
    const float* Z = MODE ? Zext : g_Z1;
    int tid = threadIdx.x;
    int c = tid & 127, half = tid >> 7;
    double s = 0.0, q = 0.0;
    for (int r = blockIdx.x * 2 + half; r < M; r += gridDim.x * 2) {
        float v = Z[(size_t)r * 128 + c];
        s += v;
        q += (double)v * v;
    }
    __shared__ double sh[512];
    sh[tid] = s;
    sh[256 + tid] = q;
    __syncthreads();
    if (tid < 128) {
        double* sum = g_stats + (MODE ? 256 : 0);
        double* sq  = g_stats + (MODE ? 384 : 128);
        atomicAdd(&sum[c], sh[tid] + sh[tid + 128]);
        atomicAdd(&sq[c],  sh[256 + tid] + sh[256 + tid + 128]);
    }
}

// ---- fold BN (mean/var/gamma/beta) into per-column scale/shift ----
template <int MODE>
__global__ void finalize_bn(const float* __restrict__ gamma,
                            const float* __restrict__ beta, int M) {
    int c = threadIdx.x;
    const double* sum = g_stats + (MODE ? 256 : 0);
    const double* sq  = g_stats + (MODE ? 384 : 128);
    double mean = sum[c] / (double)M;
    double var  = sq[c] / (double)M - mean * mean;
    float sc = gamma[c] * rsqrtf((float)var + 1e-5f);
    g_bn[MODE * 256 + c]       = sc;
    g_bn[MODE * 256 + 128 + c] = beta[c] - (float)mean * sc;
}

// ---- final: out = relu(bn2(out)) in place ----
__global__ void bn_relu_out_kernel(float* __restrict__ out, int n4) {
    int idx = blockIdx.x * blockDim.x + threadIdx.x;
    if (idx >= n4) return;
    float4 v = ((float4*)out)[idx];
    int k = (idx & 31) * 4;
    v.x = fmaxf(fmaf(v.x, g_bn[256 + k + 0], g_bn[384 + k + 0]), 0.f);
    v.y = fmaxf(fmaf(v.y, g_bn[256 + k + 1], g_bn[384 + k + 1]), 0.f);
    v.z = fmaxf(fmaf(v.z, g_bn[256 + k + 2], g_bn[384 + k + 2]), 0.f);
    v.w = fmaxf(fmaf(v.w, g_bn[256 + k + 3], g_bn[384 + k + 3]), 0.f);
    ((float4*)out)[idx] = v;
}

extern "C" void kernel_launch(void* const* d_in, const int* in_sizes, int n_in,
                              void* d_out, int out_size) {
    const float* x   = (const float*)d_in[0];
    const void*  ei  = d_in[1];
    // d_in[2] = batch (unused; single graph, BN is over all nodes)
    const float* eps = (const float*)d_in[3];
    const float* W1  = (const float*)d_in[4];
    const float* b1  = (const float*)d_in[5];
    const float* g1  = (const float*)d_in[6];
    const float* be1 = (const float*)d_in[7];
    const float* W2  = (const float*)d_in[8];
    const float* b2  = (const float*)d_in[9];
    const float* g2  = (const float*)d_in[10];
    const float* be2 = (const float*)d_in[11];
    float* out = (float*)d_out;

    int N = in_sizes[0] / 128;
    int E = in_sizes[1] / 2;
    int n4 = N * 32;

    cudaFuncSetAttribute(gemm_bn<0>, cudaFuncAttributeMaxDynamicSharedMemorySize, GEMM_SMEM_BYTES);
    cudaFuncSetAttribute(gemm_bn<1>, cudaFuncAttributeMaxDynamicSharedMemorySize, GEMM_SMEM_BYTES);

    detect_kernel<<<1, 256>>>(ei, E, N);
    prep_kernel<<<(33280 + 255) / 256, 256>>>(W1, W2);
    init_h_kernel<<<(n4 + 255) / 256, 256>>>(x, eps, n4);
    scatter_kernel<<<(E + 7) / 8, 256>>>(x, ei, E);

    int gblocks = (N + 63) / 64;
    gemm_bn<0><<<gblocks, 128, GEMM_SMEM_BYTES>>>(b1, nullptr, N);
    colstats_kernel<0><<<256, 256>>>(nullptr, N);
    finalize_bn<0><<<1, 128>>>(g1, be1, N);

    gemm_bn<1><<<gblocks, 128, GEMM_SMEM_BYTES>>>(b2, out, N);
    colstats_kernel<1><<<256, 256>>>(out, N);
    finalize_bn<1><<<1, 128>>>(g2, be2, N);

    bn_relu_out_kernel<<<(n4 + 255) / 256, 256>>>(out, n4);
}

// round 3
// speedup vs baseline: 1.4796x; 1.4796x over previous
#include <cuda_runtime.h>

#define NNODES 50000
#define DFEAT 128

// ---- scratch (device globals: no allocation allowed) ----
__device__ __align__(256) float  g_H[NNODES * DFEAT];   // h = (1+eps)*x + agg
__device__ __align__(256) float  g_Z1[NNODES * DFEAT];  // pre-BN output of linear1
__device__ __align__(256) float  g_Wt1[DFEAT * DFEAT];  // W1 transposed [k][o]
__device__ __align__(256) float  g_Wt2[DFEAT * DFEAT];  // W2 transposed [k][o]
__device__ __align__(256) double g_stats[512];          // sum1,sq1,sum2,sq2 (128 each)
__device__ __align__(256) float  g_bn[512];             // scale1,shift1 ; scale2,shift2
__device__ int g_is64;                                  // edge_index dtype flag

// ---- prep: transpose weights + zero stats + probe edge dtype ----
__global__ void prep_kernel(const float* __restrict__ W1, const float* __restrict__ W2,
                            const void* eiv, int E, int N) {
    int idx = blockIdx.x * blockDim.x + threadIdx.x;
    if (idx < 16384) {
        g_Wt1[(idx & 127) * 128 + (idx >> 7)] = W1[idx];
    } else if (idx < 32768) {
        int j = idx - 16384;
        g_Wt2[(j & 127) * 128 + (j >> 7)] = W2[j];
    } else if (idx < 33280) {
        g_stats[idx - 32768] = 0.0;
    }
    // block 0: dtype probe (int64 values in-range [0,N) for 1024 entries <=> int64)
    if (blockIdx.x == 0) {
        __shared__ int bad;
        if (threadIdx.x == 0) bad = 0;
        __syncthreads();
        const long long* p = (const long long*)eiv;
        int n = E < 1024 ? E : 1024;
        for (int i = threadIdx.x; i < n; i += blockDim.x) {
            long long v = p[i];
            if (v < 0 || v >= (long long)N) atomicOr(&bad, 1);
        }
        __syncthreads();
        if (threadIdx.x == 0) g_is64 = bad ? 0 : 1;
    }
}

// ---- h = (1+eps) * x ----
__global__ void init_h_kernel(const float* __restrict__ x, const float* __restrict__ eps, int n4) {
    int idx = blockIdx.x * blockDim.x + threadIdx.x;
    if (idx >= n4) return;
    float c = 1.0f + *eps;
    float4 v = ((const float4*)x)[idx];
    v.x *= c; v.y *= c; v.z *= c; v.w *= c;
    ((float4*)g_H)[idx] = v;
}

// ---- edge scatter-add: 4 edges per warp (MLP=4), vector L2 reductions ----
__global__ void __launch_bounds__(256) scatter_kernel(const float* __restrict__ x,
                                                      const void* __restrict__ eiv, int E) {
    int lane = threadIdx.x & 31;
    int warp = (blockIdx.x * blockDim.x + threadIdx.x) >> 5;
    int e0 = warp * 4;
    if (e0 >= E) return;
    int is64 = g_is64;

    if (e0 + 4 <= E) {
        long long s[4], d[4];
        if (is64) {
            const long long* ei = (const long long*)eiv;
#pragma unroll
            for (int k = 0; k < 4; k++) { s[k] = __ldg(&ei[e0 + k]); d[k] = __ldg(&ei[E + e0 + k]); }
        } else {
            const int* ei = (const int*)eiv;
#pragma unroll
            for (int k = 0; k < 4; k++) { s[k] = __ldg(&ei[e0 + k]); d[k] = __ldg(&ei[E + e0 + k]); }
        }
        float4 v[4];
#pragma unroll
        for (int k = 0; k < 4; k++)
            v[k] = __ldg(((const float4*)(x + s[k] * 128)) + lane);
#pragma unroll
        for (int k = 0; k < 4; k++) {
            float* dp = g_H + d[k] * 128 + (lane << 2);
            asm volatile("red.global.add.v4.f32 [%0], {%1,%2,%3,%4};"
                         :: "l"(dp), "f"(v[k].x), "f"(v[k].y), "f"(v[k].z), "f"(v[k].w) : "memory");
        }
    } else {
        for (int e = e0; e < E; e++) {
            long long s, d;
            if (is64) {
                const long long* ei = (const long long*)eiv;
                s = __ldg(&ei[e]); d = __ldg(&ei[E + e]);
            } else {
                const int* ei = (const int*)eiv;
                s = __ldg(&ei[e]); d = __ldg(&ei[E + e]);
            }
            float4 v = __ldg(((const float4*)(x + s * 128)) + lane);
            float* dp = g_H + d * 128 + (lane << 2);
            asm volatile("red.global.add.v4.f32 [%0], {%1,%2,%3,%4};"
                         :: "l"(dp), "f"(v.x), "f"(v.y), "f"(v.z), "f"(v.w) : "memory");
        }
    }
}

// ---- GEMM: Z[m][o] = bias[o] + sum_k f(A[m][k]) * W[o][k]
// MODE 0: A=g_H,  f=identity,             Z=g_Z1,  stats->g_stats[0/128]
// MODE 1: A=g_Z1, f=relu(bn1(.)) (fused), Z=Zout,  stats->g_stats[256/384]
// Block: 64 rows x 128 cols (full K=128 in smem). 128 threads, 8x8 reg tile.
// Column sum/sumsq computed in epilogue (fused colstats).
#define GEMM_SMEM_BYTES ((64 * 129 + 128 * 128 + 256) * 4)

template <int MODE>
__global__ void __launch_bounds__(128) gemm_bn(const float* __restrict__ bias,
                                               float* __restrict__ Zout, int M) {
    extern __shared__ float smem[];
    float (*As)[129] = (float(*)[129])smem;       // 64 x 129 (padded)
    float* Ws      = smem + 64 * 129;             // [k][o], 128x128
    float* s_scale = Ws + 16384;
    float* s_shift = s_scale + 128;

    const float* A  = MODE ? g_Z1 : g_H;
    const float* Wt = MODE ? g_Wt2 : g_Wt1;
    float* Z        = MODE ? Zout : g_Z1;

    int tid = threadIdx.x;
    int m0 = blockIdx.x * 64;

    if (MODE) {
        s_scale[tid] = g_bn[tid];
        s_shift[tid] = g_bn[128 + tid];
        __syncthreads();
    }

    // load W tile (coalesced, already transposed in gmem)
    const float4* Wt4 = (const float4*)Wt;
    float4* Ws4 = (float4*)Ws;
#pragma unroll
    for (int i = 0; i < 32; i++)
        Ws4[i * 128 + tid] = Wt4[i * 128 + tid];

    // load A tile (apply BN1+ReLU on the fly in MODE 1)
#pragma unroll
    for (int i = 0; i < 16; i++) {
        int idx = i * 128 + tid;
        int m = idx >> 5, k4 = idx & 31;
        int gm = m0 + m;
        float4 v = make_float4(0.f, 0.f, 0.f, 0.f);
        if (gm < M) v = ((const float4*)A)[(size_t)gm * 32 + k4];
        int k = k4 * 4;
        if (MODE) {
            v.x = fmaxf(fmaf(v.x, s_scale[k + 0], s_shift[k + 0]), 0.f);
            v.y = fmaxf(fmaf(v.y, s_scale[k + 1], s_shift[k + 1]), 0.f);
            v.z = fmaxf(fmaf(v.z, s_scale[k + 2], s_shift[k + 2]), 0.f);
            v.w = fmaxf(fmaf(v.w, s_scale[k + 3], s_shift[k + 3]), 0.f);
        }
        As[m][k + 0] = v.x; As[m][k + 1] = v.y;
        As[m][k + 2] = v.z; As[m][k + 3] = v.w;
    }
    __syncthreads();

    int ty = tid >> 4, tx = tid & 15;
    float acc[8][8];
#pragma unroll
    for (int i = 0; i < 8; i++)
#pragma unroll
        for (int j = 0; j < 8; j++) acc[i][j] = 0.f;

#pragma unroll 4
    for (int k = 0; k < 128; k++) {
        float a[8];
#pragma unroll
        for (int i = 0; i < 8; i++) a[i] = As[ty * 8 + i][k];
        float4 wa = *(const float4*)(Ws + k * 128 + tx * 8);
        float4 wb = *(const float4*)(Ws + k * 128 + tx * 8 + 4);
        float w[8] = {wa.x, wa.y, wa.z, wa.w, wb.x, wb.y, wb.z, wb.w};
#pragma unroll
        for (int i = 0; i < 8; i++)
#pragma unroll
            for (int j = 0; j < 8; j++)
                acc[i][j] = fmaf(a[i], w[j], acc[i][j]);
    }

    // epilogue: add bias, store, and accumulate per-column sum / sumsq
    float bi[8];
#pragma unroll
    for (int j = 0; j < 8; j++) bi[j] = bias[tx * 8 + j];

    float csum[8], csq[8];
#pragma unroll
    for (int j = 0; j < 8; j++) { csum[j] = 0.f; csq[j] = 0.f; }

#pragma unroll
    for (int i = 0; i < 8; i++) {
        int gm = m0 + ty * 8 + i;
        if (gm < M) {
            float o[8];
#pragma unroll
            for (int j = 0; j < 8; j++) {
                o[j] = acc[i][j] + bi[j];
                csum[j] += o[j];
                csq[j]  += o[j] * o[j];
            }
            float4* zp = (float4*)(Z + (size_t)gm * 128);
            zp[tx * 2]     = make_float4(o[0], o[1], o[2], o[3]);
            zp[tx * 2 + 1] = make_float4(o[4], o[5], o[6], o[7]);
        }
    }

    // reduce stats across the 8 ty-rows via smem (reuse As space), then atomic
    __syncthreads();
    float* rsum = smem;          // [8][128]
    float* rsq  = smem + 1024;   // [8][128]
#pragma unroll
    for (int j = 0; j < 8; j++) {
        rsum[ty * 128 + tx * 8 + j] = csum[j];
        rsq [ty * 128 + tx * 8 + j] = csq[j];
    }
    __syncthreads();
    {
        int c = tid;  // 128 threads = 128 columns
        float s = 0.f, q = 0.f;
#pragma unroll
        for (int r = 0; r < 8; r++) {
            s += rsum[r * 128 + c];
            q += rsq [r * 128 + c];
        }
        double* sum = g_stats + (MODE ? 256 : 0);
        double* sq  = g_stats + (MODE ? 384 : 128);
        atomicAdd(&sum[c], (double)s);
        atomicAdd(&sq[c],  (double)q);
    }
}

// ---- fold BN (mean/var/gamma/beta) into per-column scale/shift ----
template <int MODE>
__global__ void finalize_bn(const float* __restrict__ gamma,
                            const float* __restrict__ beta, int M) {
    int c = threadIdx.x;
    const double* sum = g_stats + (MODE ? 256 : 0);
    const double* sq  = g_stats + (MODE ? 384 : 128);
    double mean = sum[c] / (double)M;
    double var  = sq[c] / (double)M - mean * mean;
    float sc = gamma[c] * rsqrtf((float)var + 1e-5f);
    g_bn[MODE * 256 + c]       = sc;
    g_bn[MODE * 256 + 128 + c] = beta[c] - (float)mean * sc;
}

// ---- final: out = relu(bn2(out)) in place ----
__global__ void bn_relu_out_kernel(float* __restrict__ out, int n4) {
    int idx = blockIdx.x * blockDim.x + threadIdx.x;
    if (idx >= n4) return;
    float4 v = ((float4*)out)[idx];
    int k = (idx & 31) * 4;
    v.x = fmaxf(fmaf(v.x, g_bn[256 + k + 0], g_bn[384 + k + 0]), 0.f);
    v.y = fmaxf(fmaf(v.y, g_bn[256 + k + 1], g_bn[384 + k + 1]), 0.f);
    v.z = fmaxf(fmaf(v.z, g_bn[256 + k + 2], g_bn[384 + k + 2]), 0.f);
    v.w = fmaxf(fmaf(v.w, g_bn[256 + k + 3], g_bn[384 + k + 3]), 0.f);
    ((float4*)out)[idx] = v;
}

extern "C" void kernel_launch(void* const* d_in, const int* in_sizes, int n_in,
                              void* d_out, int out_size) {
    const float* x   = (const float*)d_in[0];
    const void*  ei  = d_in[1];
    // d_in[2] = batch (unused; single graph, BN is over all nodes)
    const float* eps = (const float*)d_in[3];
    const float* W1  = (const float*)d_in[4];
    const float* b1  = (const float*)d_in[5];
    const float* g1  = (const float*)d_in[6];
    const float* be1 = (const float*)d_in[7];
    const float* W2  = (const float*)d_in[8];
    const float* b2  = (const float*)d_in[9];
    const float* g2  = (const float*)d_in[10];
    const float* be2 = (const float*)d_in[11];
    float* out = (float*)d_out;

    int N = in_sizes[0] / 128;
    int E = in_sizes[1] / 2;
    int n4 = N * 32;

    cudaFuncSetAttribute(gemm_bn<0>, cudaFuncAttributeMaxDynamicSharedMemorySize, GEMM_SMEM_BYTES);
    cudaFuncSetAttribute(gemm_bn<1>, cudaFuncAttributeMaxDynamicSharedMemorySize, GEMM_SMEM_BYTES);

    prep_kernel<<<(33280 + 255) / 256, 256>>>(W1, W2, ei, E, N);
    init_h_kernel<<<(n4 + 255) / 256, 256>>>(x, eps, n4);
    // 4 edges per warp -> E/4 warps -> E/32 blocks of 256
    scatter_kernel<<<(E + 31) / 32, 256>>>(x, ei, E);

    int gblocks = (N + 63) / 64;
    gemm_bn<0><<<gblocks, 128, GEMM_SMEM_BYTES>>>(b1, nullptr, N);
    finalize_bn<0><<<1, 128>>>(g1, be1, N);

    gemm_bn<1><<<gblocks, 128, GEMM_SMEM_BYTES>>>(b2, out, N);
    finalize_bn<1><<<1, 128>>>(g2, be2, N);

    bn_relu_out_kernel<<<(n4 + 255) / 256, 256>>>(out, n4);
}